// round 6
// baseline (speedup 1.0000x reference)
#include <cuda_runtime.h>
#include <cuda_bf16.h>
#include <cstdint>

// RecentAttention: N=500000 tokens, B=10000 sessions x L=50, H=128.
// K1: g_a[s] = x[last_ixs[s]] @ W1^T + b1 + b2       (bf16 mma GEMM, 79 tiles)
// K2: persistent; per tile (2 sessions = 100 rows, padded to 128):
//     C = x_tile @ W2^T (bf16 mma) ; h = sigmoid(C + a[seg]) ; e = h.q + qb
//     per-session softmax(e) -> alpha ; out[s] = sum alpha_i * x_i (fp32)

#define SA 136                  // smem row stride in bf16 elems (bank-conflict-free)
#define NTILE2 5000

__device__ float g_a[10000 * 128];

__device__ __forceinline__ void st4bf(__nv_bfloat16* p, float4 v) {
    *(__nv_bfloat162*)p       = __floats2bfloat162_rn(v.x, v.y);
    *(__nv_bfloat162*)(p + 2) = __floats2bfloat162_rn(v.z, v.w);
}

__device__ __forceinline__ float sigmoid_f(float x) {
    float t;
    asm("tanh.approx.f32 %0, %1;" : "=f"(t) : "f"(x * 0.5f));
    return fmaf(t, 0.5f, 0.5f);
}

#define MMA16816(C, A, B0, B1)                                              \
    asm volatile("mma.sync.aligned.m16n8k16.row.col.f32.bf16.bf16.f32 "    \
        "{%0,%1,%2,%3}, {%4,%5,%6,%7}, {%8,%9}, {%0,%1,%2,%3};"            \
        : "+f"((C)[0]), "+f"((C)[1]), "+f"((C)[2]), "+f"((C)[3])           \
        : "r"((A)[0]), "r"((A)[1]), "r"((A)[2]), "r"((A)[3]),              \
          "r"(B0), "r"(B1))

// Shared mma mainloop: C[2][8][4] = A(128x128) @ Wsm^T, warp w owns
// m-tiles {2*(w/2), 2*(w/2)+1} x n-tiles [(w&1)*8, (w&1)*8+8).
__device__ __forceinline__ void mma_128x128(
    const __nv_bfloat16* Asm, const __nv_bfloat16* Wsm,
    int warp, int lane, float c[2][8][4])
{
    int mw = warp >> 1, noct = (warp & 1) * 8;
    #pragma unroll
    for (int ks = 0; ks < 8; ks++) {
        uint32_t a[2][4];
        #pragma unroll
        for (int mi = 0; mi < 2; mi++) {
            const __nv_bfloat16* ap =
                Asm + ((mw * 2 + mi) * 16 + (lane >> 2)) * SA + ks * 16 + (lane & 3) * 2;
            a[mi][0] = *(const uint32_t*)ap;
            a[mi][1] = *(const uint32_t*)(ap + 8 * SA);
            a[mi][2] = *(const uint32_t*)(ap + 8);
            a[mi][3] = *(const uint32_t*)(ap + 8 * SA + 8);
        }
        #pragma unroll
        for (int ni = 0; ni < 8; ni++) {
            const __nv_bfloat16* bp =
                Wsm + ((noct + ni) * 8 + (lane >> 2)) * SA + ks * 16 + (lane & 3) * 2;
            uint32_t b0 = *(const uint32_t*)bp;
            uint32_t b1 = *(const uint32_t*)(bp + 8);
            MMA16816(c[0][ni], a[0], b0, b1);
            MMA16816(c[1][ni], a[1], b0, b1);
        }
    }
}

// ---------------- K1: per-session bias a[s] ----------------
__global__ void __launch_bounds__(256, 1) k1_abias(
    const float* __restrict__ x, const float* __restrict__ W1,
    const float* __restrict__ b1, const float* __restrict__ b2,
    const int* __restrict__ last_ixs)
{
    extern __shared__ char smraw[];
    __nv_bfloat16* Asm = (__nv_bfloat16*)smraw;            // 128*SA*2 = 34816
    __nv_bfloat16* Wsm = (__nv_bfloat16*)(smraw + 34816);  // 34816
    int*   li = (int*)(smraw + 69632);                      // 512
    float* bs = (float*)(smraw + 70144);                    // 512

    int tid = threadIdx.x, warp = tid >> 5, lane = tid & 31;
    int base = blockIdx.x * 128;
    int valid = min(128, 10000 - base);

    if (tid < 128) {
        li[tid] = (tid < valid) ? last_ixs[base + tid] : 0;
        bs[tid] = b1[tid] + b2[tid];
    }
    #pragma unroll
    for (int j = 0; j < 16; j++) {                  // W1 -> bf16 smem
        int f4 = tid + j * 256, row = f4 >> 5, c4 = f4 & 31;
        st4bf(Wsm + row * SA + c4 * 4, ((const float4*)W1)[f4]);
    }
    __syncthreads();
    #pragma unroll
    for (int j = 0; j < 16; j++) {                  // gather last rows -> bf16
        int f4 = tid + j * 256, row = f4 >> 5, c4 = f4 & 31;
        float4 v = make_float4(0.f, 0.f, 0.f, 0.f);
        if (row < valid) v = ((const float4*)(x + (size_t)li[row] * 128))[c4];
        st4bf(Asm + row * SA + c4 * 4, v);
    }
    __syncthreads();

    float c[2][8][4] = {};
    mma_128x128(Asm, Wsm, warp, lane, c);

    int mw = warp >> 1, noct = (warp & 1) * 8;
    #pragma unroll
    for (int mi = 0; mi < 2; mi++)
        #pragma unroll
        for (int ni = 0; ni < 8; ni++) {
            int col = (noct + ni) * 8 + (lane & 3) * 2;
            #pragma unroll
            for (int r2 = 0; r2 < 2; r2++) {
                int row = (mw * 2 + mi) * 16 + (lane >> 2) + 8 * r2;
                if (row < valid) {
                    int s = base + row;
                    g_a[s * 128 + col]     = c[mi][ni][2 * r2]     + bs[col];
                    g_a[s * 128 + col + 1] = c[mi][ni][2 * r2 + 1] + bs[col + 1];
                }
            }
        }
}

// ---------------- K2: persistent main kernel ----------------
__device__ __forceinline__ void prefetch_x(float* dst, const float* src, int tid) {
    #pragma unroll
    for (int j = 0; j < 13; j++) {
        int i = tid + j * 256;
        if (i < 3200) {
            uint32_t d = (uint32_t)__cvta_generic_to_shared(dst + i * 4);
            asm volatile("cp.async.cg.shared.global [%0], [%1], 16;"
                         :: "r"(d), "l"(src + i * 4) : "memory");
        }
    }
    asm volatile("cp.async.commit_group;" ::: "memory");
}

__global__ void __launch_bounds__(256, 1) k2_main(
    const float* __restrict__ x, const float* __restrict__ W2,
    const float* __restrict__ q, const float* __restrict__ qbp,
    float* __restrict__ out)
{
    extern __shared__ char smraw[];
    float* xf0 = (float*)smraw;                              // 12800 f = 51200 B
    float* xf1 = (float*)(smraw + 51200);                    // 51200
    __nv_bfloat16* Asm = (__nv_bfloat16*)(smraw + 102400);   // 34816
    __nv_bfloat16* Wsm = (__nv_bfloat16*)(smraw + 137216);   // 34816
    float* a_sm   = (float*)(smraw + 172032);                // 1024
    float* qsm    = (float*)(smraw + 173056);                // 512
    float* e_part = (float*)(smraw + 173568);                // 1024 (2 planes x 128)
    float* alpha  = (float*)(smraw + 174592);                // 512

    int tid = threadIdx.x, warp = tid >> 5, lane = tid & 31;
    int mw = warp >> 1, noct = (warp & 1) * 8;
    float qb = qbp[0];

    #pragma unroll
    for (int j = 0; j < 16; j++) {                   // W2 -> bf16 smem (once)
        int f4 = tid + j * 256, row = f4 >> 5, c4 = f4 & 31;
        st4bf(Wsm + row * SA + c4 * 4, ((const float4*)W2)[f4]);
    }
    #pragma unroll
    for (int j = 0; j < 34; j++)                     // zero A (pad rows stay 0)
        ((uint32_t*)Asm)[tid + j * 256] = 0u;
    if (tid < 128) qsm[tid] = q[tid];

    int t0 = blockIdx.x, stride = gridDim.x;
    if (t0 < NTILE2) prefetch_x(xf0, x + (size_t)t0 * 12800, tid);

    int it = 0;
    for (int t = t0; t < NTILE2; t += stride, it++) {
        float* xf = (it & 1) ? xf1 : xf0;
        asm volatile("cp.async.wait_group 0;" ::: "memory");
        __syncthreads();                             // xf ready; prev tile done

        int tn = t + stride;
        if (tn < NTILE2) prefetch_x((it & 1) ? xf0 : xf1, x + (size_t)tn * 12800, tid);

        a_sm[tid] = g_a[2 * t * 128 + tid];          // a rows for both sessions
        #pragma unroll
        for (int j = 0; j < 13; j++) {               // fp32 tile -> bf16 A
            int f4 = tid + j * 256;
            if (f4 < 3200) {
                int row = f4 >> 5, c4 = f4 & 31;
                st4bf(Asm + row * SA + c4 * 4, ((const float4*)xf)[f4]);
            }
        }
        __syncthreads();

        float c[2][8][4] = {};
        mma_128x128(Asm, Wsm, warp, lane, c);

        // e partials: pe[mi][r2] = sum_cols q*sigmoid(C + a)
        float pe[2][2] = {};
        #pragma unroll
        for (int ni = 0; ni < 8; ni++) {
            int col = (noct + ni) * 8 + (lane & 3) * 2;
            float q0 = qsm[col], q1 = qsm[col + 1];
            float a00 = a_sm[col], a01 = a_sm[col + 1];
            float a10 = a_sm[128 + col], a11 = a_sm[128 + col + 1];
            #pragma unroll
            for (int mi = 0; mi < 2; mi++)
                #pragma unroll
                for (int r2 = 0; r2 < 2; r2++) {
                    int row = (mw * 2 + mi) * 16 + (lane >> 2) + 8 * r2;
                    if (row < 100) {
                        bool s1 = row >= 50;
                        float h0 = sigmoid_f(c[mi][ni][2 * r2]     + (s1 ? a10 : a00));
                        float h1 = sigmoid_f(c[mi][ni][2 * r2 + 1] + (s1 ? a11 : a01));
                        pe[mi][r2] = fmaf(q0, h0, fmaf(q1, h1, pe[mi][r2]));
                    }
                }
        }
        #pragma unroll
        for (int mi = 0; mi < 2; mi++)
            #pragma unroll
            for (int r2 = 0; r2 < 2; r2++) {
                float v = pe[mi][r2];
                v += __shfl_xor_sync(0xffffffffu, v, 1);
                v += __shfl_xor_sync(0xffffffffu, v, 2);
                if ((lane & 3) == 0) {
                    int row = (mw * 2 + mi) * 16 + (lane >> 2) + 8 * r2;
                    e_part[(warp & 1) * 128 + row] = v;
                }
            }
        __syncthreads();

        if (warp < 2) {                              // per-session softmax (50 rows)
            int rb = warp * 50;
            int i1 = rb + lane;
            bool v2 = lane < 18;
            int i2 = rb + 32 + lane;
            float e1 = e_part[i1] + e_part[128 + i1] + qb;
            float e2 = v2 ? (e_part[i2] + e_part[128 + i2] + qb) : -1e30f;
            float m = fmaxf(e1, e2);
            #pragma unroll
            for (int o = 16; o; o >>= 1) m = fmaxf(m, __shfl_xor_sync(0xffffffffu, m, o));
            float z1 = __expf(e1 - m);
            float z2 = v2 ? __expf(e2 - m) : 0.f;
            float s = z1 + z2;
            #pragma unroll
            for (int o = 16; o; o >>= 1) s += __shfl_xor_sync(0xffffffffu, s, o);
            float inv = __frcp_rn(s);
            alpha[i1] = z1 * inv;
            if (v2) alpha[i2] = z2 * inv;
        }
        __syncthreads();

        // pooling: out[2t+s][col] = sum_j alpha * x (fp32 from smem)
        int s = tid >> 7, col = tid & 127;
        const float* xr = xf + s * 50 * 128 + col;
        const float* al = alpha + s * 50;
        float acc = 0.f;
        #pragma unroll 10
        for (int j = 0; j < 50; j++) acc = fmaf(al[j], xr[j * 128], acc);
        out[(size_t)(2 * t + s) * 128 + col] = acc;
    }
}

extern "C" void kernel_launch(void* const* d_in, const int* in_sizes, int n_in,
                              void* d_out, int out_size)
{
    const float* x   = (const float*)d_in[0];
    const float* W1w = (const float*)d_in[1];
    const float* W1b = (const float*)d_in[2];
    const float* W2w = (const float*)d_in[3];
    const float* W2b = (const float*)d_in[4];
    const float* qw  = (const float*)d_in[5];
    const float* qb  = (const float*)d_in[6];
    const int* last  = (const int*)d_in[8];
    float* out = (float*)d_out;

    int smem1 = 70656;
    int smem2 = 175104;
    cudaFuncSetAttribute(k1_abias, cudaFuncAttributeMaxDynamicSharedMemorySize, smem1);
    cudaFuncSetAttribute(k2_main,  cudaFuncAttributeMaxDynamicSharedMemorySize, smem2);

    int nsm = 148;
    cudaDeviceGetAttribute(&nsm, cudaDevAttrMultiProcessorCount, 0);

    k1_abias<<<79, 256, smem1>>>(x, W1w, W1b, W2b, last);
    k2_main<<<nsm, 256, smem2>>>(x, W2w, qw, qb, out);
}

// round 7
// speedup vs baseline: 1.3593x; 1.3593x over previous
#include <cuda_runtime.h>
#include <cuda_bf16.h>
#include <cstdint>

// RecentAttention: N=500000 tokens, B=10000 sessions x L=50, H=128.
// K1: g_a[s] = x[last_ixs[s]] @ W1^T + b1 + b2    (bf16 mma, 157 CTAs x 64 rows)
// K2: persistent, 2 CTAs/SM; per tile (2 sessions = 100 rows, padded to 128):
//     C = x_tile @ W2^T (bf16 mma via ldmatrix) ; h = sigmoid(C + a[seg])
//     e = h.q + qb ; per-session softmax -> alpha ; out = sum alpha*x (fp32, from L2)

#define SA 136                  // smem row stride in bf16 elems (conflict-free)
#define NTILE2 5000

__device__ float g_a[10000 * 128];

__device__ __forceinline__ void st4bf(__nv_bfloat16* p, float4 v) {
    *(__nv_bfloat162*)p       = __floats2bfloat162_rn(v.x, v.y);
    *(__nv_bfloat162*)(p + 2) = __floats2bfloat162_rn(v.z, v.w);
}

__device__ __forceinline__ float sigmoid_f(float x) {
    float t;
    asm("tanh.approx.f32 %0, %1;" : "=f"(t) : "f"(x * 0.5f));
    return fmaf(t, 0.5f, 0.5f);
}

#define MMA16816(C, A, B0, B1)                                              \
    asm volatile("mma.sync.aligned.m16n8k16.row.col.f32.bf16.bf16.f32 "    \
        "{%0,%1,%2,%3}, {%4,%5,%6,%7}, {%8,%9}, {%0,%1,%2,%3};"            \
        : "+f"((C)[0]), "+f"((C)[1]), "+f"((C)[2]), "+f"((C)[3])           \
        : "r"((A)[0]), "r"((A)[1]), "r"((A)[2]), "r"((A)[3]),              \
          "r"(B0), "r"(B1))

#define LDSM4(R, a)                                                         \
    asm volatile("ldmatrix.sync.aligned.m8n8.x4.shared.b16 {%0,%1,%2,%3}, [%4];" \
        : "=r"((R)[0]), "=r"((R)[1]), "=r"((R)[2]), "=r"((R)[3]) : "r"(a))

// One 32-row x 32-col x 128-K pass. abase/bbase are lane-adjusted shared addrs.
// A tiles: (q&1)*8+r rows, (q>>1)*8 k  -> regs {a0,a1,a2,a3} of m16k16.
// B tiles: (q>>1)*8+r rows(n), (q&1)*8 k -> regs {b0(n),b1(n),b0(n+8),b1(n+8)}.
__device__ __forceinline__ void mma_pass(uint32_t abase, uint32_t bbase,
                                         float c[2][4][4]) {
    #pragma unroll
    for (int ks = 0; ks < 8; ks++) {
        uint32_t A0[4], A1[4], B0[4], B1[4];
        LDSM4(A0, abase + ks * 32);
        LDSM4(A1, abase + 16 * SA * 2 + ks * 32);
        LDSM4(B0, bbase + ks * 32);
        LDSM4(B1, bbase + 16 * SA * 2 + ks * 32);
        MMA16816(c[0][0], A0, B0[0], B0[1]);
        MMA16816(c[0][1], A0, B0[2], B0[3]);
        MMA16816(c[0][2], A0, B1[0], B1[1]);
        MMA16816(c[0][3], A0, B1[2], B1[3]);
        MMA16816(c[1][0], A1, B0[0], B0[1]);
        MMA16816(c[1][1], A1, B0[2], B0[3]);
        MMA16816(c[1][2], A1, B1[0], B1[1]);
        MMA16816(c[1][3], A1, B1[2], B1[3]);
    }
}

// ---------------- K1: per-session bias a[s] = x[last]@W1^T + b1 + b2 -------
__global__ void __launch_bounds__(256, 1) k1_abias(
    const float* __restrict__ x, const float* __restrict__ W1,
    const float* __restrict__ b1, const float* __restrict__ b2,
    const int* __restrict__ last_ixs)
{
    extern __shared__ char smraw[];
    __nv_bfloat16* Asm = (__nv_bfloat16*)smraw;            // 34816
    __nv_bfloat16* Wsm = (__nv_bfloat16*)(smraw + 34816);  // 34816
    int*   li = (int*)(smraw + 69632);                      // 512
    float* bs = (float*)(smraw + 70144);                    // 512

    int tid = threadIdx.x, warp = tid >> 5, lane = tid & 31;
    int base = blockIdx.x * 64;
    int valid = min(64, 10000 - base);

    if (tid < 128) {
        li[tid] = (tid < valid) ? last_ixs[base + tid] : 0;
        bs[tid] = b1[tid] + b2[tid];
    }
    #pragma unroll
    for (int j = 0; j < 16; j++) {                  // W1 -> bf16 smem
        int f4 = tid + j * 256, row = f4 >> 5, c4 = f4 & 31;
        st4bf(Wsm + row * SA + c4 * 4, ((const float4*)W1)[f4]);
    }
    __syncthreads();
    #pragma unroll
    for (int j = 0; j < 16; j++) {                  // gather last rows -> bf16
        int f4 = tid + j * 256, row = f4 >> 5, c4 = f4 & 31;
        float4 v = make_float4(0.f, 0.f, 0.f, 0.f);
        if (row < valid) v = ((const float4*)(x + (size_t)li[row] * 128))[c4];
        st4bf(Asm + row * SA + c4 * 4, v);
    }
    __syncthreads();

    int mw = warp >> 1, m0 = mw * 32;
    int q = lane >> 3, r7 = lane & 7;
    uint32_t asm_u = (uint32_t)__cvta_generic_to_shared(Asm);
    uint32_t wsm_u = (uint32_t)__cvta_generic_to_shared(Wsm);
    uint32_t abase = asm_u + 2 * ((m0 + (q & 1) * 8 + r7) * SA + (q >> 1) * 8);

    #pragma unroll
    for (int p = 0; p < 2; p++) {
        int n0 = (warp & 1) * 64 + p * 32;
        uint32_t bbase = wsm_u + 2 * ((n0 + (q >> 1) * 8 + r7) * SA + (q & 1) * 8);
        float c[2][4][4] = {};
        mma_pass(abase, bbase, c);
        #pragma unroll
        for (int mi = 0; mi < 2; mi++)
            #pragma unroll
            for (int ni = 0; ni < 4; ni++) {
                int col = n0 + ni * 8 + (lane & 3) * 2;
                #pragma unroll
                for (int r2 = 0; r2 < 2; r2++) {
                    int row = m0 + mi * 16 + (lane >> 2) + 8 * r2;
                    if (row < valid) {
                        size_t o = (size_t)(base + row) * 128 + col;
                        g_a[o]     = c[mi][ni][2 * r2]     + bs[col];
                        g_a[o + 1] = c[mi][ni][2 * r2 + 1] + bs[col + 1];
                    }
                }
            }
    }
}

// ---------------- K2: persistent main kernel (2 CTAs/SM) ----------------
__global__ void __launch_bounds__(256, 2) k2_main(
    const float* __restrict__ x, const float* __restrict__ W2,
    const float* __restrict__ q, const float* __restrict__ qbp,
    float* __restrict__ out)
{
    extern __shared__ char smraw[];
    __nv_bfloat16* Wsm = (__nv_bfloat16*)smraw;              // 34816
    __nv_bfloat16* Asm = (__nv_bfloat16*)(smraw + 34816);    // 34816
    float* a_sm   = (float*)(smraw + 69632);                 // 1024
    float* qsm    = (float*)(smraw + 70656);                 // 512
    float* e_part = (float*)(smraw + 71168);                 // 1024 (2 planes x 128)
    float* alpha  = (float*)(smraw + 72192);                 // 512

    int tid = threadIdx.x, warp = tid >> 5, lane = tid & 31;
    int mw = warp >> 1, m0 = mw * 32;
    int qq = lane >> 3, r7 = lane & 7;
    float qb = qbp[0];

    #pragma unroll
    for (int j = 0; j < 16; j++) {                   // W2 -> bf16 smem (once)
        int f4 = tid + j * 256, row = f4 >> 5, c4 = f4 & 31;
        st4bf(Wsm + row * SA + c4 * 4, ((const float4*)W2)[f4]);
    }
    #pragma unroll
    for (int j = 0; j < 34; j++)                     // zero A (pad rows stay 0)
        ((uint32_t*)Asm)[tid + j * 256] = 0u;
    if (tid < 128) qsm[tid] = q[tid];

    uint32_t asm_u = (uint32_t)__cvta_generic_to_shared(Asm);
    uint32_t wsm_u = (uint32_t)__cvta_generic_to_shared(Wsm);
    uint32_t abase = asm_u + 2 * ((m0 + (qq & 1) * 8 + r7) * SA + (qq >> 1) * 8);
    uint32_t bb[2];
    #pragma unroll
    for (int p = 0; p < 2; p++) {
        int n0 = (warp & 1) * 64 + p * 32;
        bb[p] = wsm_u + 2 * ((n0 + (qq >> 1) * 8 + r7) * SA + (qq & 1) * 8);
    }
    __syncthreads();

    for (int t = blockIdx.x; t < NTILE2; t += gridDim.x) {
        const float* xt = x + (size_t)t * 12800;

        // ---- fill: x tile -> bf16 Asm (batched LDG for MLP) ----
        float4 v[13];
        #pragma unroll
        for (int j = 0; j < 13; j++) {
            int f4 = tid + j * 256;
            if (f4 < 3200) v[j] = ((const float4*)xt)[f4];
        }
        a_sm[tid] = g_a[(size_t)t * 256 + tid];
        #pragma unroll
        for (int j = 0; j < 13; j++) {
            int f4 = tid + j * 256;
            if (f4 < 3200) st4bf(Asm + (f4 >> 5) * SA + (f4 & 31) * 4, v[j]);
        }
        __syncthreads();                              // Asm/a_sm ready

        // ---- MMA + fused epilogue (two 32-col passes) ----
        float pe[2][2] = {};
        #pragma unroll
        for (int p = 0; p < 2; p++) {
            float c[2][4][4] = {};
            mma_pass(abase, bb[p], c);
            int nbase = (warp & 1) * 64 + p * 32;
            #pragma unroll
            for (int ni = 0; ni < 4; ni++) {
                int col = nbase + ni * 8 + (lane & 3) * 2;
                float q0 = qsm[col], q1 = qsm[col + 1];
                float a00 = a_sm[col], a01 = a_sm[col + 1];
                float a10 = a_sm[128 + col], a11 = a_sm[128 + col + 1];
                #pragma unroll
                for (int mi = 0; mi < 2; mi++)
                    #pragma unroll
                    for (int r2 = 0; r2 < 2; r2++) {
                        int row = m0 + mi * 16 + (lane >> 2) + 8 * r2;
                        if (row < 100) {
                            bool s1 = row >= 50;
                            float h0 = sigmoid_f(c[mi][ni][2 * r2]     + (s1 ? a10 : a00));
                            float h1 = sigmoid_f(c[mi][ni][2 * r2 + 1] + (s1 ? a11 : a01));
                            pe[mi][r2] = fmaf(q0, h0, fmaf(q1, h1, pe[mi][r2]));
                        }
                    }
            }
        }
        #pragma unroll
        for (int mi = 0; mi < 2; mi++)
            #pragma unroll
            for (int r2 = 0; r2 < 2; r2++) {
                float vv = pe[mi][r2];
                vv += __shfl_xor_sync(0xffffffffu, vv, 1);
                vv += __shfl_xor_sync(0xffffffffu, vv, 2);
                if ((lane & 3) == 0) {
                    int row = m0 + mi * 16 + (lane >> 2) + 8 * r2;
                    e_part[(warp & 1) * 128 + row] = vv;
                }
            }
        __syncthreads();

        if (warp < 2) {                               // per-session softmax (50 rows)
            int rb = warp * 50;
            int i1 = rb + lane;
            bool v2 = lane < 18;
            int i2 = rb + 32 + lane;
            float e1 = e_part[i1] + e_part[128 + i1] + qb;
            float e2 = v2 ? (e_part[i2] + e_part[128 + i2] + qb) : -1e30f;
            float m = fmaxf(e1, e2);
            #pragma unroll
            for (int o = 16; o; o >>= 1) m = fmaxf(m, __shfl_xor_sync(0xffffffffu, m, o));
            float z1 = __expf(e1 - m);
            float z2 = v2 ? __expf(e2 - m) : 0.f;
            float s = z1 + z2;
            #pragma unroll
            for (int o = 16; o; o >>= 1) s += __shfl_xor_sync(0xffffffffu, s, o);
            float inv = __frcp_rn(s);
            alpha[i1] = z1 * inv;
            if (v2) alpha[i2] = z2 * inv;
        }
        __syncthreads();

        // ---- pooling: out[2t+s][col] = sum_j alpha_j * x_j[col] (fp32, L2 hits)
        int s = tid >> 7, col = tid & 127;
        const float* xr = xt + s * 6400 + col;
        const float* al = alpha + s * 50;
        float acc = 0.f;
        #pragma unroll 10
        for (int j = 0; j < 50; j++) acc = fmaf(al[j], xr[j * 128], acc);
        out[(size_t)(2 * t + s) * 128 + col] = acc;
        __syncthreads();                              // alpha safe to overwrite
    }
}

extern "C" void kernel_launch(void* const* d_in, const int* in_sizes, int n_in,
                              void* d_out, int out_size)
{
    const float* x   = (const float*)d_in[0];
    const float* W1w = (const float*)d_in[1];
    const float* W1b = (const float*)d_in[2];
    const float* W2w = (const float*)d_in[3];
    const float* W2b = (const float*)d_in[4];
    const float* qw  = (const float*)d_in[5];
    const float* qb  = (const float*)d_in[6];
    const int* last  = (const int*)d_in[8];
    float* out = (float*)d_out;

    int smem1 = 70656;
    int smem2 = 72704;
    cudaFuncSetAttribute(k1_abias, cudaFuncAttributeMaxDynamicSharedMemorySize, smem1);
    cudaFuncSetAttribute(k2_main,  cudaFuncAttributeMaxDynamicSharedMemorySize, smem2);

    int nsm = 148;
    cudaDeviceGetAttribute(&nsm, cudaDevAttrMultiProcessorCount, 0);

    k1_abias<<<157, 256, smem1>>>(x, W1w, W1b, W2b, last);
    k2_main<<<2 * nsm, 256, smem2>>>(x, W2w, qw, qb, out);
}